// round 17
// baseline (speedup 1.0000x reference)
#include <cuda_runtime.h>
#include <math.h>

#define B_   16
#define T_   8192
#define CF   256            // feature channels (GLU output)
#define LOUT 8196           // padded x_evs length
#define FTN  8224           // firstt entries per batch (>= LOUT + BM + 1)
#define BM   16             // bins per pooling block

// ---- output layout (flat float32, reference tuple order) ----
#define OFF_XE  0
#define OFF_LEN (B_ * CF * LOUT)                 // 33,570,816
#define OFF_BM  (OFF_LEN + B_)                   // bmoves
#define OFF_W   (OFF_BM + B_ * T_)               // weights

// ---------------- f32x2 packed helpers ----------------
typedef unsigned long long u64;
__device__ __forceinline__ u64 pack2(float lo, float hi) {
    u64 r; asm("mov.b64 %0, {%1, %2};" : "=l"(r) : "f"(lo), "f"(hi)); return r;
}
__device__ __forceinline__ void unpack2(u64 v, float& lo, float& hi) {
    asm("mov.b64 {%0, %1}, %2;" : "=f"(lo), "=f"(hi) : "l"(v));
}
__device__ __forceinline__ u64 fma2(u64 a, u64 b, u64 c) {
    u64 d; asm("fma.rn.f32x2 %0, %1, %2, %3;" : "=l"(d) : "l"(a), "l"(b), "l"(c)); return d;
}
__device__ __forceinline__ u64 lds2(const float* p) {   // 8B-aligned shared load
    return *reinterpret_cast<const u64*>(p);
}

// ---------------- device scratch (static; no allocation) ----------------
__device__ float g_wa[512 * 9];       // BN-folded main conv weights
__device__ float g_ba[512];
__device__ float g_w1f[62 * 32];      // [(ic*31+k)*32 + c]
__device__ float g_b1f[32];
__device__ float g_w2f[480 * 32];     // [(ic*15+k)*32 + c]
__device__ float g_b2f[32];
__device__ float g_moves[B_ * T_];    // sigmoid * norm_mean
__device__ float g_w1w[B_ * T_];      // (1-frac) * weights
__device__ float g_w2w[B_ * T_];      // frac * weights
__device__ int   g_fl[B_ * T_];
__device__ int   g_firstt[B_ * FTN];  // first t with fl >= m  (init T_)
__device__ float g_feat[B_ * T_ * CF]; // [b][t][c], 128 MiB

// ======================= K0: fold BN into weights =======================
__global__ void k_setup(const float* __restrict__ conv_w,
                        const float* __restrict__ bn_g, const float* __restrict__ bn_b,
                        const float* __restrict__ bn_m, const float* __restrict__ bn_v,
                        const float* __restrict__ p1_w, const float* __restrict__ p1_b,
                        const float* __restrict__ g1, const float* __restrict__ b1,
                        const float* __restrict__ m1, const float* __restrict__ v1,
                        const float* __restrict__ p2_w, const float* __restrict__ p2_b,
                        const float* __restrict__ g2, const float* __restrict__ b2,
                        const float* __restrict__ m2, const float* __restrict__ v2)
{
    int gt  = blockIdx.x * blockDim.x + threadIdx.x;
    int nth = gridDim.x * blockDim.x;
    for (int c = gt; c < 512; c += nth) {
        float s = bn_g[c] * rsqrtf(bn_v[c] + 1e-3f);
        g_ba[c] = bn_b[c] - bn_m[c] * s;
        #pragma unroll
        for (int k = 0; k < 9; k++) g_wa[c * 9 + k] = conv_w[c * 9 + k] * s;
    }
    for (int c = gt; c < 32; c += nth) {
        float s1 = g1[c] * rsqrtf(v1[c] + 1e-5f);
        g_b1f[c] = p1_b[c] * s1 + (b1[c] - m1[c] * s1);
        for (int ic = 0; ic < 2; ic++)
            for (int k = 0; k < 31; k++)
                g_w1f[(ic * 31 + k) * 32 + c] = p1_w[(c * 2 + ic) * 31 + k] * s1;
        float s2 = g2[c] * rsqrtf(v2[c] + 1e-5f);
        g_b2f[c] = p2_b[c] * s2 + (b2[c] - m2[c] * s2);
        for (int ic = 0; ic < 32; ic++)
            for (int k = 0; k < 15; k++)
                g_w2f[(ic * 15 + k) * 32 + c] = p2_w[(c * 32 + ic) * 15 + k] * s2;
    }
}

__global__ void k_init(void)
{
    int i = blockIdx.x * blockDim.x + threadIdx.x;
    if (i < B_ * FTN) g_firstt[i] = T_;
}

// ======================= K-feat: main conv + GLU (f32x2 over t-pairs) ==========
// grid (T_/64, B_), 256 threads (one per channel)
__global__ __launch_bounds__(256) void k_feat(const float* __restrict__ x)
{
    __shared__ __align__(8) float xs[80];   // window [t0-4, t0+68)
    __shared__ __align__(8) float xsd[80];  // xsd[i] = xs[i+1]
    int b  = blockIdx.y;
    int t0 = blockIdx.x * 64;
    int c  = threadIdx.x;
    const float* xb = x + b * T_;
    for (int i = c; i < 72; i += 256) {
        int gp = t0 - 4 + i;
        float v = (gp >= 0 && gp < T_) ? xb[gp] : 0.f;
        xs[i] = v;
        if (i >= 1) xsd[i - 1] = v;
    }
    __syncthreads();
    u64 wA2[9], wG2[9];
    #pragma unroll
    for (int k = 0; k < 9; k++) {
        float wa = g_wa[c * 9 + k];
        float wg = g_wa[(c + 256) * 9 + k];
        wA2[k] = pack2(wa, wa);
        wG2[k] = pack2(wg, wg);
    }
    float bA = g_ba[c], bG = g_ba[c + 256];
    u64 bA2 = pack2(bA, bA), bG2 = pack2(bG, bG);
    float* fo = g_feat + ((size_t)(b * T_ + t0)) * CF + c;
    for (int t = 0; t < 64; t += 2) {
        u64 a2 = bA2, g2v = bG2;
        #pragma unroll
        for (int k = 0; k < 9; k++) {
            // pair (xs[t+k], xs[t+1+k]); t even -> aligned in xs for even k, in xsd for odd k
            u64 xv2 = ((k & 1) == 0) ? lds2(xs + t + k) : lds2(xsd + t + k - 1);
            a2  = fma2(wA2[k], xv2, a2);
            g2v = fma2(wG2[k], xv2, g2v);
        }
        float a0, a1, g0, g1v;
        unpack2(a2, a0, a1);
        unpack2(g2v, g0, g1v);
        fo[(size_t)t * CF]       = a0 / (1.f + expf(-g0));
        fo[(size_t)(t + 1) * CF] = a1 / (1.f + expf(-g1v));
    }
}

// ======================= K1: fused predictor =======================
// grid (T_/128, B_), 256 threads, dynamic smem.
// s-index (stage1): global t = (T0-14)+s, s in [0,158)
// u-index (stage2): global t = (T0-7)+u,  u in [0,144)
// Inter-stage padding: stage outputs at global t outside [0,T) must be EXACTLY 0.
#define XW     192
#define S1STR  162                       // even stride for aligned float2 loads
#define SM_XS  0
#define SM_S1  (SM_XS + 2 * XW)          // 384
#define SM_S1D (SM_S1 + 32 * S1STR)      // 384 + 5184
#define SM_S2  (SM_S1D + 32 * S1STR)     // 384 + 10368
#define SMEM_PRED_FLOATS (SM_S2 + 144 * 33)
#define SMEM_PRED_BYTES  (SMEM_PRED_FLOATS * 4)   // 62016

__global__ __launch_bounds__(256) void k_pred(const float* __restrict__ x,
                                              const float* __restrict__ p3_w,
                                              const float* __restrict__ p3_b,
                                              const float* __restrict__ norm_mean,
                                              float* __restrict__ out)
{
    extern __shared__ __align__(16) float smem[];
    float* xs  = smem + SM_XS;
    float* s1s = smem + SM_S1;    // s1s[c*S1STR + s]
    float* s1d = smem + SM_S1D;   // s1d[i] = s1s[i+1] (per-row shifted copy)
    float* s2s = smem + SM_S2;    // s2s[u*33 + c]

    int b   = blockIdx.y;
    int T0  = blockIdx.x * 128;
    int tid = threadIdx.x;
    const float* xb = x + b * T_;

    // x window [T0-29, T0+163), zero padded
    for (int i = tid; i < XW; i += 256) {
        int gp = T0 - 29 + i;
        float v = (gp >= 0 && gp < T_) ? xb[gp] : 0.f;
        xs[i] = v;
        xs[XW + i] = v * v;
    }
    __syncthreads();

    // ---- stage1: p1 conv (k=31, 2 in-ch) + BN + swish (scalar) ----
    {
        int c  = tid & 31;
        int r0 = tid >> 5;   // 0..7
        float acc[20];
        float bias = g_b1f[c];
        #pragma unroll
        for (int i = 0; i < 20; i++) acc[i] = bias;
        #pragma unroll
        for (int ic = 0; ic < 2; ic++) {
            for (int k = 0; k < 31; k++) {
                float w = g_w1f[(ic * 31 + k) * 32 + c];
                #pragma unroll
                for (int i = 0; i < 20; i++)
                    acc[i] = fmaf(w, xs[ic * XW + r0 + 8 * i + k], acc[i]);
            }
        }
        #pragma unroll
        for (int i = 0; i < 20; i++) {
            int   s   = r0 + 8 * i;
            int   gt1 = T0 - 14 + s;           // global t of this stage1 value
            float v   = acc[i];
            float sg  = 1.f / (1.f + expf(-v));
            float r   = (gt1 >= 0 && gt1 < T_) ? (v * sg) : 0.f;  // pad mask
            s1s[c * S1STR + s] = r;
            if (s >= 1) s1d[c * S1STR + s - 1] = r;
        }
    }
    __syncthreads();

    // ---- stage2: p2 conv (k=15, 32 in-ch) + BN + swish  [f32x2 packed] ----
    // acc2[j2] packs outputs (u0+2*j2, u0+2*j2+1). Pass A = even k, pass B = odd k
    // (k-reorder within an ic; ~1ulp effect).
    {
        int c  = tid & 31;
        int g  = tid >> 5;
        int u0 = g * 18;     // even
        u64 acc2[9];
        float bias = g_b2f[c];
        u64 b2v = pack2(bias, bias);
        #pragma unroll
        for (int j2 = 0; j2 < 9; j2++) acc2[j2] = b2v;

        for (int ic = 0; ic < 32; ic++) {
            const float* rowE = s1s + ic * S1STR + u0;
            const float* rowO = s1d + ic * S1STR + u0;
            // pass A: even k, pairs (r[2m], r[2m+1]) direct from s1s
            {
                u64 pe[16];
                #pragma unroll
                for (int m = 0; m < 16; m++) pe[m] = lds2(rowE + 2 * m);
                #pragma unroll
                for (int k = 0; k < 15; k += 2) {
                    float w = g_w2f[(ic * 15 + k) * 32 + c];
                    u64 w2 = pack2(w, w);
                    int h = k >> 1;
                    #pragma unroll
                    for (int j2 = 0; j2 < 9; j2++)
                        acc2[j2] = fma2(w2, pe[j2 + h], acc2[j2]);
                }
            }
            // pass B: odd k, pairs (r[o], r[o+1]) (o odd) aligned in s1d at o-1
            {
                u64 po[15];
                #pragma unroll
                for (int m = 0; m < 15; m++) po[m] = lds2(rowO + 2 * m);
                #pragma unroll
                for (int k = 1; k < 15; k += 2) {
                    float w = g_w2f[(ic * 15 + k) * 32 + c];
                    u64 w2 = pack2(w, w);
                    int h = (k - 1) >> 1;
                    #pragma unroll
                    for (int j2 = 0; j2 < 9; j2++)
                        acc2[j2] = fma2(w2, po[j2 + h], acc2[j2]);
                }
            }
        }
        #pragma unroll
        for (int j2 = 0; j2 < 9; j2++) {
            float v0, v1;
            unpack2(acc2[j2], v0, v1);
            int u  = u0 + 2 * j2;
            int gu0 = T0 - 7 + u;
            int gu1 = gu0 + 1;
            float r0v = (gu0 >= 0 && gu0 < T_) ? (v0 / (1.f + expf(-v0)) * 1.f) : 0.f;
            float r1v = (gu1 >= 0 && gu1 < T_) ? (v1 / (1.f + expf(-v1)) * 1.f) : 0.f;
            // swish = v * sigmoid(v); v/(1+e^-v) is identical
            s2s[u * 33 + c]       = r0v;
            s2s[(u + 1) * 33 + c] = r1v;
        }
    }
    __syncthreads();

    // ---- stage3: p3 conv (k=15, 2 out-ch) + sigmoid ----
    {
        int t  = tid >> 1;   // 0..127
        int oc = tid & 1;
        float acc = p3_b[oc];
        for (int ic = 0; ic < 32; ic++) {
            #pragma unroll
            for (int k = 0; k < 15; k++)
                acc = fmaf(p3_w[(oc * 32 + ic) * 15 + k], s2s[(t + k) * 33 + ic], acc);
        }
        float sg = 1.f / (1.f + expf(-acc));
        int gt = T0 + t;
        if (oc == 0) {
            out[OFF_W + b * T_ + gt] = sg;                 // weights
        } else {
            out[OFF_BM + b * T_ + gt] = sg;                // bmoves
            g_moves[b * T_ + gt] = sg * norm_mean[0];      // moves (eval renorm)
        }
    }
}

// ======================= K2: fp32 Brent-Kung cumsum + bin tables =======================
// Same association tree as jax associative_scan (fp32) for power-of-2 length.
// one block per batch row; 1024 threads
__global__ __launch_bounds__(1024) void k_scan(float* __restrict__ out)
{
    __shared__ float ps[T_];
    int b   = blockIdx.x;
    int tid = threadIdx.x;
    const float* mv = g_moves + b * T_;
    for (int t = tid; t < T_; t += 1024) ps[t] = mv[t];

    // up-sweep (reduce): pairwise sums
    for (int d = 1; d < T_; d <<= 1) {
        __syncthreads();
        int stride = d << 1;
        int cnt = T_ / stride;
        for (int i = tid; i < cnt; i += 1024) {
            int idx = (i + 1) * stride - 1;
            ps[idx] = ps[idx - d] + ps[idx];
        }
    }
    // down-sweep: fill interior prefixes
    for (int d = T_ >> 2; d >= 1; d >>= 1) {
        __syncthreads();
        int stride = d << 1;
        int cnt = T_ / stride - 1;
        for (int i = tid; i < cnt; i += 1024) {
            int idx = (i + 1) * stride - 1 + d;
            ps[idx] = ps[idx - d] + ps[idx];
        }
    }
    __syncthreads();

    const float* wt = out + OFF_W + b * T_;
    for (int t = tid; t < T_; t += 1024) {
        float pf   = ps[t];
        float flo  = floorf(pf);
        float frac = pf - flo;
        int   fl   = (int)flo;
        float w    = wt[t];
        g_fl[b * T_ + t]  = fl;
        g_w1w[b * T_ + t] = (1.f - frac) * w;
        g_w2w[b * T_ + t] = frac * w;
        int fp = (t == 0) ? -1 : (int)floorf(ps[t - 1]);
        if (fl > fp) g_firstt[b * FTN + fl] = t;   // fl steps by 0 or +1 (moves < 1)
    }
    if (tid == 0) out[OFF_LEN + b] = floorf(ps[T_ - 1]) + 2.f;   // lens = fl[-1] + 2
}

// ======================= K3: gather pooling (zero atomics) =======================
// grid (ceil(LOUT/BM), B_), 256 threads (one per channel)
__global__ __launch_bounds__(256) void k_pool(float* __restrict__ out)
{
    __shared__ float acc_s[BM][257];
    int b  = blockIdx.y;
    int m0 = blockIdx.x * BM;
    int c  = threadIdx.x;
    for (int i = c; i < BM * 257; i += 256) ((float*)acc_s)[i] = 0.f;
    __syncthreads();

    const int* ft = g_firstt + b * FTN;
    int tstart = ft[(m0 > 0) ? (m0 - 1) : 0];
    int tend   = ft[m0 + BM];
    const int*   flb = g_fl  + b * T_;
    const float* w1b = g_w1w + b * T_;
    const float* w2b = g_w2w + b * T_;
    const float* fb  = g_feat + (size_t)b * T_ * CF;

    if (tstart < tend) {
        float accA = 0.f, accB = 0.f;
        int cb = flb[tstart];
        // 1-deep prefetch (feat load is the DRAM-latency one)
        float fvn = fb[(size_t)tstart * CF + c];
        int   fn  = cb;
        float w1n = w1b[tstart], w2n = w2b[tstart];
        for (int t = tstart; t < tend; t++) {
            float fv = fvn; int f = fn; float w1v = w1n, w2v = w2n;
            int tn = t + 1;
            if (tn < tend) {
                fvn = fb[(size_t)tn * CF + c];
                fn  = flb[tn];
                w1n = w1b[tn];
                w2n = w2b[tn];
            }
            if (f != cb) {            // fl advanced by exactly 1: bin cb complete
                if (cb >= m0) acc_s[cb - m0][c] = accA;
                accA = accB;
                accB = 0.f;
                cb = f;
            }
            accA = fmaf(w1v, fv, accA);   // -> bin fl[t]
            accB = fmaf(w2v, fv, accB);   // -> bin fl[t]+1
        }
        if (cb >= m0 && cb < m0 + BM)         acc_s[cb - m0][c]     = accA;
        if (cb + 1 >= m0 && cb + 1 < m0 + BM) acc_s[cb + 1 - m0][c] = accB;
    }
    __syncthreads();

    // x_evs[b][ch][m0+m]
    for (int i = c; i < CF * BM; i += 256) {
        int ch = i >> 4;
        int m  = i & (BM - 1);
        int gm = m0 + m;
        if (gm < LOUT)
            out[OFF_XE + ((size_t)(b * CF + ch)) * LOUT + gm] = acc_s[m][ch];
    }
}

// ======================= launch =======================
extern "C" void kernel_launch(void* const* d_in, const int* in_sizes, int n_in,
                              void* d_out, int out_size)
{
    const float* x      = (const float*)d_in[0];
    const float* conv_w = (const float*)d_in[1];
    const float* bn_g   = (const float*)d_in[2];
    const float* bn_b   = (const float*)d_in[3];
    const float* bn_m   = (const float*)d_in[4];
    const float* bn_v   = (const float*)d_in[5];
    const float* p1_w   = (const float*)d_in[6];
    const float* p1_b   = (const float*)d_in[7];
    const float* g1     = (const float*)d_in[8];
    const float* b1     = (const float*)d_in[9];
    const float* m1     = (const float*)d_in[10];
    const float* v1     = (const float*)d_in[11];
    const float* p2_w   = (const float*)d_in[12];
    const float* p2_b   = (const float*)d_in[13];
    const float* g2     = (const float*)d_in[14];
    const float* b2     = (const float*)d_in[15];
    const float* m2     = (const float*)d_in[16];
    const float* v2     = (const float*)d_in[17];
    const float* p3_w   = (const float*)d_in[18];
    const float* p3_b   = (const float*)d_in[19];
    const float* nmean  = (const float*)d_in[20];
    float* out = (float*)d_out;

    cudaFuncSetAttribute(k_pred, cudaFuncAttributeMaxDynamicSharedMemorySize,
                         SMEM_PRED_BYTES);

    k_setup<<<2, 256>>>(conv_w, bn_g, bn_b, bn_m, bn_v,
                        p1_w, p1_b, g1, b1, m1, v1,
                        p2_w, p2_b, g2, b2, m2, v2);
    k_init<<<(B_ * FTN + 255) / 256, 256>>>();
    k_feat<<<dim3(T_ / 64, B_), 256>>>(x);
    k_pred<<<dim3(T_ / 128, B_), 256, SMEM_PRED_BYTES>>>(x, p3_w, p3_b, nmean, out);
    k_scan<<<B_, 1024>>>(out);
    k_pool<<<dim3((LOUT + BM - 1) / BM, B_), 256>>>(out);
}